// round 1
// baseline (speedup 1.0000x reference)
#include <cuda_runtime.h>
#include <cuda_bf16.h>

#define NBLK 1024
#define NTHR 256

// Per-block partials + completion ticket (module-scope device memory; no allocs).
__device__ float g_sum[NBLK];
__device__ int   g_cnt[NBLK];
__device__ float g_max[NBLK];
__device__ unsigned int g_done = 0;

__device__ __forceinline__ void point_acc(float x, float y, float z,
                                          float& acc_sum, int& acc_cnt, float& acc_max) {
    // Fold into positive octant: octahedron |x|+|y|+|z| <= 1 is sign-symmetric.
    float qx = fabsf(x), qy = fabsf(y), qz = fabsf(z);
    float s  = qx + qy + qz;

    // inside test: max over the 8 faces of p.n - off = s*c - c, c = fp32(1/sqrt(3))
    const float C = 0.57735026918962576f;
    bool inside = (s * C - C) <= 1e-8f;

    // nearest-vertex distance^2 (vertices are +-e_i): |p|^2 + 1 - 2*max|p_i|
    float dot = fmaf(qx, qx, fmaf(qy, qy, qz * qz));
    float mv  = fmaxf(qx, fmaxf(qy, qz));
    float d2v = dot + 1.0f - 2.0f * mv;

    // distance^2 to triangle {e1,e2,e3} (the closest triangle for any outside point)
    float t1      = s - 1.0f;
    float face_sq = t1 * t1 * (1.0f / 3.0f);
    float qmin    = fminf(qx, fminf(qy, qz));
    bool  face_ok = (3.0f * qmin >= t1);   // plane projection lands inside the triangle

    // edge e1->e2: t = clamp((q.(v-u) - u.(v-u)) / |v-u|^2) with |v-u|^2 = 2
    float ta  = __saturatef((qy - qx + 1.0f) * 0.5f);
    float dxa = qx - 1.0f + ta, dya = qy - ta;
    float e1  = fmaf(dxa, dxa, fmaf(dya, dya, qz * qz));
    // edge e2->e3
    float tb  = __saturatef((qz - qy + 1.0f) * 0.5f);
    float dyb = qy - 1.0f + tb, dzb = qz - tb;
    float e2  = fmaf(qx, qx, fmaf(dyb, dyb, dzb * dzb));
    // edge e3->e1
    float tc  = __saturatef((qx - qz + 1.0f) * 0.5f);
    float dzc = qz - 1.0f + tc, dxc = qx - tc;
    float e3  = fmaf(dxc, dxc, fmaf(qy, qy, dzc * dzc));

    float sq = fminf(e1, fminf(e2, e3));
    sq = face_ok ? face_sq : sq;

    // predicated accumulate (compiler emits SELs, no divergence cost)
    acc_sum += inside ? d2v : 0.0f;
    acc_cnt += inside ? 1 : 0;
    acc_max  = fmaxf(acc_max, inside ? 0.0f : sq);
}

__global__ void __launch_bounds__(NTHR)
palette_bound_loss_kernel(const float4* __restrict__ pts4,
                          const float*  __restrict__ pts,
                          float* __restrict__ out,
                          int n_items, int n_points) {
    float acc_sum = 0.0f;
    int   acc_cnt = 0;
    float acc_max = 0.0f;

    const int stride = gridDim.x * blockDim.x;
    for (int item = blockIdx.x * blockDim.x + threadIdx.x; item < n_items; item += stride) {
        // 3 x float4 = 12 floats = 4 points, fully coalesced
        float4 f0 = pts4[3 * item + 0];
        float4 f1 = pts4[3 * item + 1];
        float4 f2 = pts4[3 * item + 2];
        point_acc(f0.x, f0.y, f0.z, acc_sum, acc_cnt, acc_max);
        point_acc(f0.w, f1.x, f1.y, acc_sum, acc_cnt, acc_max);
        point_acc(f1.z, f1.w, f2.x, acc_sum, acc_cnt, acc_max);
        point_acc(f2.y, f2.z, f2.w, acc_sum, acc_cnt, acc_max);
    }

    // warp reduce
    #pragma unroll
    for (int o = 16; o > 0; o >>= 1) {
        acc_sum += __shfl_down_sync(0xffffffffu, acc_sum, o);
        acc_cnt += __shfl_down_sync(0xffffffffu, acc_cnt, o);
        acc_max  = fmaxf(acc_max, __shfl_down_sync(0xffffffffu, acc_max, o));
    }

    __shared__ float s_sum[NTHR / 32];
    __shared__ int   s_cnt[NTHR / 32];
    __shared__ float s_max[NTHR / 32];
    int lane = threadIdx.x & 31;
    int wid  = threadIdx.x >> 5;
    if (lane == 0) { s_sum[wid] = acc_sum; s_cnt[wid] = acc_cnt; s_max[wid] = acc_max; }
    __syncthreads();

    __shared__ bool s_is_last;
    if (threadIdx.x == 0) {
        float bs = 0.0f; int bc = 0; float bm = 0.0f;
        #pragma unroll
        for (int i = 0; i < NTHR / 32; i++) {
            bs += s_sum[i]; bc += s_cnt[i]; bm = fmaxf(bm, s_max[i]);
        }
        g_sum[blockIdx.x] = bs;
        g_cnt[blockIdx.x] = bc;
        g_max[blockIdx.x] = bm;
        __threadfence();
        unsigned int ticket = atomicAdd(&g_done, 1u);
        s_is_last = (ticket == (unsigned int)(gridDim.x - 1));
    }
    __syncthreads();

    if (s_is_last) {
        __threadfence();  // acquire side: partials from all blocks are visible
        float fs = 0.0f; int fc = 0; float fm = 0.0f;
        for (int i = threadIdx.x; i < NBLK; i += NTHR) {
            fs += g_sum[i]; fc += g_cnt[i]; fm = fmaxf(fm, g_max[i]);
        }
        #pragma unroll
        for (int o = 16; o > 0; o >>= 1) {
            fs += __shfl_down_sync(0xffffffffu, fs, o);
            fc += __shfl_down_sync(0xffffffffu, fc, o);
            fm  = fmaxf(fm, __shfl_down_sync(0xffffffffu, fm, o));
        }
        if (lane == 0) { s_sum[wid] = fs; s_cnt[wid] = fc; s_max[wid] = fm; }
        __syncthreads();
        if (threadIdx.x == 0) {
            float fs2 = 0.0f; int fc2 = 0; float fm2 = 0.0f;
            #pragma unroll
            for (int i = 0; i < NTHR / 32; i++) {
                fs2 += s_sum[i]; fc2 += s_cnt[i]; fm2 = fmaxf(fm2, s_max[i]);
            }
            // scalar tail (n_points % 4), normally empty for N = 1048576
            for (int p = n_items * 4; p < n_points; p++) {
                point_acc(pts[3 * p + 0], pts[3 * p + 1], pts[3 * p + 2], fs2, fc2, fm2);
            }
            int n_out = n_points - fc2;
            float loss_in  = (fc2   > 0) ? (0.001f * fs2 / (float)fc2) : 0.0f;
            float loss_out = (n_out > 0) ? fm2 : 0.0f;
            out[0] = loss_in + loss_out;
            g_done = 0;  // reset ticket so every graph replay starts clean
        }
    }
}

extern "C" void kernel_launch(void* const* d_in, const int* in_sizes, int n_in,
                              void* d_out, int out_size) {
    const float* pts = (const float*)d_in[0];
    int n_points = in_sizes[0] / 3;
    int n_items  = n_points / 4;   // 4 points (12 floats = 3 float4) per work item
    palette_bound_loss_kernel<<<NBLK, NTHR>>>(
        (const float4*)pts, pts, (float*)d_out, n_items, n_points);
}